// round 1
// baseline (speedup 1.0000x reference)
#include <cuda_runtime.h>
#include <math.h>

// ---------------- problem constants ----------------
#define HH 384
#define BB 16
#define CI 64
#define EE 768
#define GG 24   // coarse grid
// coarse tokens: BB*576*EE ; detail tokens: BB*64*EE ; idx: BB*64

// ---------------- scratch (device globals, no allocation) ----------------
__device__ float g_f1[(size_t)BB*CI*HH*HH];          // after conv1+bn+gelu
__device__ float g_f2[(size_t)BB*CI*HH*HH];          // after conv2+bn+gelu
__device__ float g_dmap[(size_t)BB*48*48*EE];        // detail map, [b,y48,x48,e]
__device__ float g_scores[BB*576];
__device__ int   g_topk[BB*64];

__device__ __forceinline__ float gelu_f(float v) { return v * normcdff(v); }

// ---------------- conv1: 3->64, 3x3, pad1, + BN + GELU ----------------
__global__ void conv1_kernel(const float* __restrict__ x, const float* __restrict__ w,
                             const float* __restrict__ gma, const float* __restrict__ bta,
                             const float* __restrict__ mu,  const float* __restrict__ var)
{
    __shared__ float xs[3][18][18];
    __shared__ float ws[64*27];
    __shared__ float sc[64], sh[64];
    const int tid = threadIdx.y * 16 + threadIdx.x;
    const int b  = blockIdx.z;
    const int y0 = blockIdx.y * 16, x0 = blockIdx.x * 16;

    for (int i = tid; i < 3*18*18; i += 256) {
        int ci = i / 324, r = (i % 324) / 18, cc = i % 18;
        int yy = y0 - 1 + r, xx = x0 - 1 + cc;
        float v = 0.f;
        if (yy >= 0 && yy < HH && xx >= 0 && xx < HH)
            v = x[((b*3 + ci)*HH + yy)*HH + xx];
        xs[ci][r][cc] = v;
    }
    for (int i = tid; i < 64*27; i += 256) ws[i] = w[i];
    if (tid < 64) {
        float s = gma[tid] * rsqrtf(var[tid] + 1e-5f);
        sc[tid] = s; sh[tid] = bta[tid] - mu[tid] * s;
    }
    __syncthreads();

    float win[27];
#pragma unroll
    for (int ci = 0; ci < 3; ci++)
#pragma unroll
        for (int ky = 0; ky < 3; ky++)
#pragma unroll
            for (int kx = 0; kx < 3; kx++)
                win[(ci*3 + ky)*3 + kx] = xs[ci][threadIdx.y + ky][threadIdx.x + kx];

    const int y = y0 + threadIdx.y, xg = x0 + threadIdx.x;
    for (int oc = 0; oc < 64; oc++) {
        float acc = 0.f;
#pragma unroll
        for (int i = 0; i < 27; i++) acc = fmaf(ws[oc*27 + i], win[i], acc);
        float t = acc * sc[oc] + sh[oc];
        g_f1[((b*64 + oc)*HH + y)*HH + xg] = gelu_f(t);
    }
}

// ---------------- conv2: 64->64, 3x3, pad1, + BN + GELU ----------------
// block (16,16): 16x64 spatial tile, 16 out-channels (4 oc passes via grid.z)
__global__ __launch_bounds__(256, 2)
void conv2_kernel(const float* __restrict__ w,
                  const float* __restrict__ gma, const float* __restrict__ bta,
                  const float* __restrict__ mu,  const float* __restrict__ var)
{
    __shared__ float ti[66][18];
    __shared__ float wsm[144];
    __shared__ float sc[16], sh[16];
    const int tx = threadIdx.x, ty = threadIdx.y;
    const int tid = ty * 16 + tx;
    const int bz = blockIdx.z;
    const int b = bz >> 2, ocb = (bz & 3) * 16;
    const int y0 = blockIdx.y * 64, x0 = blockIdx.x * 16;

    if (tid < 16) {
        int oc = ocb + tid;
        float s = gma[oc] * rsqrtf(var[oc] + 1e-5f);
        sc[tid] = s; sh[tid] = bta[oc] - mu[oc] * s;
    }

    float acc[4][16];
#pragma unroll
    for (int r = 0; r < 4; r++)
#pragma unroll
        for (int o = 0; o < 16; o++) acc[r][o] = 0.f;

    for (int ci = 0; ci < 64; ci++) {
        __syncthreads();
        for (int i = tid; i < 66*18; i += 256) {
            int r = i / 18, cc = i % 18;
            int yy = y0 - 1 + r, xx = x0 - 1 + cc;
            float v = 0.f;
            if (yy >= 0 && yy < HH && xx >= 0 && xx < HH)
                v = g_f1[((b*64 + ci)*HH + yy)*HH + xx];
            ti[r][cc] = v;
        }
        if (tid < 144) {
            int o = tid / 9, j = tid % 9;
            wsm[tid] = w[(ocb + o)*576 + ci*9 + j];
        }
        __syncthreads();

        float win[4][9];
#pragma unroll
        for (int r = 0; r < 4; r++)
#pragma unroll
            for (int ky = 0; ky < 3; ky++)
#pragma unroll
                for (int kx = 0; kx < 3; kx++)
                    win[r][ky*3 + kx] = ti[ty + 16*r + ky][tx + kx];

#pragma unroll
        for (int o = 0; o < 16; o++) {
#pragma unroll
            for (int j = 0; j < 9; j++) {
                float wv = wsm[o*9 + j];
#pragma unroll
                for (int r = 0; r < 4; r++)
                    acc[r][o] = fmaf(wv, win[r][j], acc[r][o]);
            }
        }
    }

#pragma unroll
    for (int r = 0; r < 4; r++) {
        int y = y0 + ty + 16*r;
#pragma unroll
        for (int o = 0; o < 16; o++) {
            float t = acc[r][o] * sc[o] + sh[o];
            g_f2[((b*64 + ocb + o)*HH + y)*HH + x0 + tx] = gelu_f(t);
        }
    }
}

// ---------------- implicit GEMM: 128x128 tile, BK=16, 8x8 per thread ----------------
// MODE 0: coarse  (A = 16x16 patches of f2, K=16384) -> out (d_out coarse region)
// MODE 1: detail  (A =  8x8  patches of f2, K= 4096) -> g_dmap [m][n]
// MODE 2: merge   (A = gathered dmap rows,  K= 3072) -> out (d_out detail region)
template<int MODE>
__global__ __launch_bounds__(256, 2)
void gemm_kernel(const float* __restrict__ W, const float* __restrict__ bias,
                 float* __restrict__ out)
{
    constexpr int K = (MODE == 0) ? 16384 : ((MODE == 1) ? 4096 : 3072);
    __shared__ __align__(16) float As[16][128];
    __shared__ __align__(16) float Bs[16][128];

    const int tid = threadIdx.x;
    const int bm = blockIdx.y, bn = blockIdx.x;
    const int lr = tid >> 1;           // 0..127 : row within tile (for loads)
    const int kq = (tid & 1) * 8;      // 0 or 8 : k sub-offset (for loads)
    const int arow = bm * 128 + lr;
    const int brow = bn * 128 + lr;

    int baseA = 0, baseY = 0, baseX = 0;
    if (MODE == 0) {
        int b = arow / 576; int cell = arow % 576;
        int gy = cell / 24, gx = cell % 24;
        baseA = ((b*64)*HH + gy*16)*HH + gx*16;
    } else if (MODE == 1) {
        int b = arow / 2304; int r2 = arow % 2304;
        int yy = r2 / 48, xx = r2 % 48;
        baseA = ((b*64)*HH + yy*8)*HH + xx*8;
    } else {
        int cell = g_topk[arow];
        int b = arow >> 6;
        baseY = b*48 + 2*(cell / 24);
        baseX = 2*(cell % 24);
    }
    const float* wp = W + (long)brow * K;

    float acc[8][8];
#pragma unroll
    for (int i = 0; i < 8; i++)
#pragma unroll
        for (int j = 0; j < 8; j++) acc[i][j] = 0.f;

    const int ty = tid >> 4, txn = tid & 15;

    for (int kc = 0; kc < K; kc += 16) {
        const int k0 = kc + kq;
        const float* ap;
        if (MODE == 0) {
            int c = k0 >> 8; int rem = k0 & 255;
            ap = g_f2 + baseA + c*(HH*HH) + (rem >> 4)*HH + (rem & 15);
        } else if (MODE == 1) {
            int c = k0 >> 6; int rem = k0 & 63;
            ap = g_f2 + baseA + c*(HH*HH) + (rem >> 3)*HH;
        } else {
            int dyx = k0 / 768; int e = k0 - dyx*768;
            ap = g_dmap + ((baseY + (dyx >> 1))*48 + baseX + (dyx & 1))*768 + e;
        }
        float4 a0 = *(const float4*)(ap);
        float4 a1 = *(const float4*)(ap + 4);
        float4 b0 = *(const float4*)(wp + k0);
        float4 b1 = *(const float4*)(wp + k0 + 4);

        __syncthreads();
        As[kq+0][lr] = a0.x; As[kq+1][lr] = a0.y; As[kq+2][lr] = a0.z; As[kq+3][lr] = a0.w;
        As[kq+4][lr] = a1.x; As[kq+5][lr] = a1.y; As[kq+6][lr] = a1.z; As[kq+7][lr] = a1.w;
        Bs[kq+0][lr] = b0.x; Bs[kq+1][lr] = b0.y; Bs[kq+2][lr] = b0.z; Bs[kq+3][lr] = b0.w;
        Bs[kq+4][lr] = b1.x; Bs[kq+5][lr] = b1.y; Bs[kq+6][lr] = b1.z; Bs[kq+7][lr] = b1.w;
        __syncthreads();

#pragma unroll
        for (int kk = 0; kk < 16; kk++) {
            float4 av0 = *(const float4*)&As[kk][ty*8];
            float4 av1 = *(const float4*)&As[kk][ty*8 + 4];
            float4 bv0 = *(const float4*)&Bs[kk][txn*8];
            float4 bv1 = *(const float4*)&Bs[kk][txn*8 + 4];
            float av[8] = {av0.x, av0.y, av0.z, av0.w, av1.x, av1.y, av1.z, av1.w};
            float bv[8] = {bv0.x, bv0.y, bv0.z, bv0.w, bv1.x, bv1.y, bv1.z, bv1.w};
#pragma unroll
            for (int i = 0; i < 8; i++)
#pragma unroll
                for (int j = 0; j < 8; j++)
                    acc[i][j] = fmaf(av[i], bv[j], acc[i][j]);
        }
    }

    float* op = (MODE == 1) ? g_dmap : out;
    const int n0 = bn*128 + txn*8;
    float4 bb0 = *(const float4*)&bias[n0];
    float4 bb1 = *(const float4*)&bias[n0 + 4];
#pragma unroll
    for (int i = 0; i < 8; i++) {
        long mrow = bm*128 + ty*8 + i;
        float4 o0, o1;
        o0.x = acc[i][0] + bb0.x; o0.y = acc[i][1] + bb0.y;
        o0.z = acc[i][2] + bb0.z; o0.w = acc[i][3] + bb0.w;
        o1.x = acc[i][4] + bb1.x; o1.y = acc[i][5] + bb1.y;
        o1.z = acc[i][6] + bb1.z; o1.w = acc[i][7] + bb1.w;
        *(float4*)&op[mrow*768 + n0]     = o0;
        *(float4*)&op[mrow*768 + n0 + 4] = o1;
    }
}

// ---------------- per-patch variance score ----------------
__global__ void score_kernel()
{
    const int bi = blockIdx.x;           // b*576 + cell
    const int b = bi / 576, cell = bi % 576;
    const int gy = cell / 24, gx = cell % 24;
    const int tid = threadIdx.x;
    const int c = tid >> 2, q = tid & 3;
    const float* base = g_f2 + ((b*64 + c)*HH + gy*16)*HH + gx*16;
    float s = 0.f, ss = 0.f;
#pragma unroll 4
    for (int i = 0; i < 64; i++) {
        int p = q*64 + i;
        float v = base[(p >> 4)*HH + (p & 15)];
        s += v; ss = fmaf(v, v, ss);
    }
    s  += __shfl_down_sync(0xffffffffu, s, 2);
    s  += __shfl_down_sync(0xffffffffu, s, 1);
    ss += __shfl_down_sync(0xffffffffu, ss, 2);
    ss += __shfl_down_sync(0xffffffffu, ss, 1);
    __shared__ float cv[64];
    if ((tid & 3) == 0) {
        float mean = s * (1.f/256.f);
        cv[c] = ss * (1.f/256.f) - mean*mean;
    }
    __syncthreads();
    if (tid < 32) {
        float v = cv[tid] + cv[tid + 32];
        for (int off = 16; off > 0; off >>= 1)
            v += __shfl_down_sync(0xffffffffu, v, off);
        if (tid == 0) g_scores[bi] = v * (1.f/64.f);
    }
}

// ---------------- top-64 of 576, descending, ties -> lowest index ----------------
__global__ void topk_kernel(float* __restrict__ out_idx)
{
    const int b = blockIdx.x, tid = threadIdx.x;
    __shared__ float s[576];
    __shared__ float rv[256];
    __shared__ int   ri[256];
    for (int i = tid; i < 576; i += 256) s[i] = g_scores[b*576 + i];
    __syncthreads();
    for (int k = 0; k < 64; k++) {
        float bv = s[tid]; int bidx = tid;
        if (tid + 256 < 576) { float v = s[tid + 256]; if (v > bv) { bv = v; bidx = tid + 256; } }
        if (tid + 512 < 576) { float v = s[tid + 512]; if (v > bv) { bv = v; bidx = tid + 512; } }
        rv[tid] = bv; ri[tid] = bidx;
        __syncthreads();
        for (int off = 128; off > 0; off >>= 1) {
            if (tid < off) {
                float v2 = rv[tid + off]; int i2 = ri[tid + off];
                if (v2 > rv[tid] || (v2 == rv[tid] && i2 < ri[tid])) { rv[tid] = v2; ri[tid] = i2; }
            }
            __syncthreads();
        }
        if (tid == 0) {
            int best = ri[0];
            g_topk[b*64 + k] = best;
            out_idx[b*64 + k] = (float)best;
            s[best] = -3.0e38f;
        }
        __syncthreads();
    }
}

// ---------------- launch ----------------
extern "C" void kernel_launch(void* const* d_in, const int* in_sizes, int n_in,
                              void* d_out, int out_size)
{
    (void)in_sizes; (void)n_in; (void)out_size;
    const float* x        = (const float*)d_in[0];
    const float* conv1_w  = (const float*)d_in[1];
    const float* bn1_g    = (const float*)d_in[2];
    const float* bn1_b    = (const float*)d_in[3];
    const float* bn1_m    = (const float*)d_in[4];
    const float* bn1_v    = (const float*)d_in[5];
    const float* conv2_w  = (const float*)d_in[6];
    const float* bn2_g    = (const float*)d_in[7];
    const float* bn2_b    = (const float*)d_in[8];
    const float* bn2_m    = (const float*)d_in[9];
    const float* bn2_v    = (const float*)d_in[10];
    const float* coarse_w = (const float*)d_in[11];
    const float* coarse_b = (const float*)d_in[12];
    const float* detail_w = (const float*)d_in[13];
    const float* detail_b = (const float*)d_in[14];
    const float* merge_w  = (const float*)d_in[15];
    const float* merge_b  = (const float*)d_in[16];
    float* out = (float*)d_out;

    const long OFF1 = 16L*576*768;            // coarse tokens
    const long OFF2 = OFF1 + 16L*64*768;      // detail tokens

    conv1_kernel<<<dim3(24,24,16), dim3(16,16)>>>(x, conv1_w, bn1_g, bn1_b, bn1_m, bn1_v);
    conv2_kernel<<<dim3(24,6,64),  dim3(16,16)>>>(conv2_w, bn2_g, bn2_b, bn2_m, bn2_v);

    // coarse tokens -> out[0 .. OFF1)
    gemm_kernel<0><<<dim3(6,72), 256>>>(coarse_w, coarse_b, out);

    // variance scores + top-k (writes float idx to out[OFF2..])
    score_kernel<<<9216, 256>>>();
    topk_kernel<<<16, 256>>>(out + OFF2);

    // detail map (all 48x48 positions) -> g_dmap
    gemm_kernel<1><<<dim3(6,288), 256>>>(detail_w, detail_b, nullptr);

    // merge only the selected K=64 cells -> out[OFF1 .. OFF2)
    gemm_kernel<2><<<dim3(6,8), 256>>>(merge_w, merge_b, out + OFF1);
}

// round 3
// speedup vs baseline: 1.1729x; 1.1729x over previous
#include <cuda_runtime.h>
#include <math.h>
#include <stdint.h>
#include <mma.h>

using namespace nvcuda;

// ---------------- problem constants ----------------
#define HH 384
#define BB 16
#define CI 64
#define EE 768

// ---------------- scratch (device globals, no allocation) ----------------
__device__ float g_f1[(size_t)BB*CI*HH*HH];          // after conv1+bn+gelu
__device__ float g_f2[(size_t)BB*CI*HH*HH];          // after conv2+bn+gelu
__device__ float g_dmap[(size_t)BB*48*48*EE];        // detail map (NO bias), [b,y48,x48,e]
__device__ float g_scores[BB*576];
__device__ int   g_topk[BB*64];
__device__ float g_mbias[EE];                        // effective merge bias

__device__ __forceinline__ float gelu_f(float v) { return v * normcdff(v); }

// ---------------- conv1: 3->64, 3x3, pad1, + BN + GELU ----------------
__global__ void conv1_kernel(const float* __restrict__ x, const float* __restrict__ w,
                             const float* __restrict__ gma, const float* __restrict__ bta,
                             const float* __restrict__ mu,  const float* __restrict__ var)
{
    __shared__ float xs[3][18][18];
    __shared__ float ws[64*27];
    __shared__ float sc[64], sh[64];
    const int tid = threadIdx.y * 16 + threadIdx.x;
    const int b  = blockIdx.z;
    const int y0 = blockIdx.y * 16, x0 = blockIdx.x * 16;

    for (int i = tid; i < 3*18*18; i += 256) {
        int ci = i / 324, r = (i % 324) / 18, cc = i % 18;
        int yy = y0 - 1 + r, xx = x0 - 1 + cc;
        float v = 0.f;
        if (yy >= 0 && yy < HH && xx >= 0 && xx < HH)
            v = x[((b*3 + ci)*HH + yy)*HH + xx];
        xs[ci][r][cc] = v;
    }
    for (int i = tid; i < 64*27; i += 256) ws[i] = w[i];
    if (tid < 64) {
        float s = gma[tid] * rsqrtf(var[tid] + 1e-5f);
        sc[tid] = s; sh[tid] = bta[tid] - mu[tid] * s;
    }
    __syncthreads();

    float win[27];
#pragma unroll
    for (int ci = 0; ci < 3; ci++)
#pragma unroll
        for (int ky = 0; ky < 3; ky++)
#pragma unroll
            for (int kx = 0; kx < 3; kx++)
                win[(ci*3 + ky)*3 + kx] = xs[ci][threadIdx.y + ky][threadIdx.x + kx];

    const int y = y0 + threadIdx.y, xg = x0 + threadIdx.x;
    for (int oc = 0; oc < 64; oc++) {
        float acc = 0.f;
#pragma unroll
        for (int i = 0; i < 27; i++) acc = fmaf(ws[oc*27 + i], win[i], acc);
        float t = acc * sc[oc] + sh[oc];
        g_f1[((b*64 + oc)*HH + y)*HH + xg] = gelu_f(t);
    }
}

// ---------------- conv2: 64->64, 3x3, pad1, + BN + GELU ----------------
__global__ __launch_bounds__(256, 2)
void conv2_kernel(const float* __restrict__ w,
                  const float* __restrict__ gma, const float* __restrict__ bta,
                  const float* __restrict__ mu,  const float* __restrict__ var)
{
    __shared__ float ti[66][18];
    __shared__ float wsm[144];
    __shared__ float sc[16], sh[16];
    const int tx = threadIdx.x, ty = threadIdx.y;
    const int tid = ty * 16 + tx;
    const int bz = blockIdx.z;
    const int b = bz >> 2, ocb = (bz & 3) * 16;
    const int y0 = blockIdx.y * 64, x0 = blockIdx.x * 16;

    if (tid < 16) {
        int oc = ocb + tid;
        float s = gma[oc] * rsqrtf(var[oc] + 1e-5f);
        sc[tid] = s; sh[tid] = bta[oc] - mu[oc] * s;
    }

    float acc[4][16];
#pragma unroll
    for (int r = 0; r < 4; r++)
#pragma unroll
        for (int o = 0; o < 16; o++) acc[r][o] = 0.f;

    for (int ci = 0; ci < 64; ci++) {
        __syncthreads();
        for (int i = tid; i < 66*18; i += 256) {
            int r = i / 18, cc = i % 18;
            int yy = y0 - 1 + r, xx = x0 - 1 + cc;
            float v = 0.f;
            if (yy >= 0 && yy < HH && xx >= 0 && xx < HH)
                v = g_f1[((b*64 + ci)*HH + yy)*HH + xx];
            ti[r][cc] = v;
        }
        if (tid < 144) {
            int o = tid / 9, j = tid % 9;
            wsm[tid] = w[(ocb + o)*576 + ci*9 + j];
        }
        __syncthreads();

        float win[4][9];
#pragma unroll
        for (int r = 0; r < 4; r++)
#pragma unroll
            for (int ky = 0; ky < 3; ky++)
#pragma unroll
                for (int kx = 0; kx < 3; kx++)
                    win[r][ky*3 + kx] = ti[ty + 16*r + ky][tx + kx];

#pragma unroll
        for (int o = 0; o < 16; o++) {
#pragma unroll
            for (int j = 0; j < 9; j++) {
                float wv = wsm[o*9 + j];
#pragma unroll
                for (int r = 0; r < 4; r++)
                    acc[r][o] = fmaf(wv, win[r][j], acc[r][o]);
            }
        }
    }

#pragma unroll
    for (int r = 0; r < 4; r++) {
        int y = y0 + ty + 16*r;
#pragma unroll
        for (int o = 0; o < 16; o++) {
            float t = acc[r][o] * sc[o] + sh[o];
            g_f2[((b*64 + ocb + o)*HH + y)*HH + x0 + tx] = gelu_f(t);
        }
    }
}

// ---------------- WMMA tf32 implicit GEMM: 128x128 tile, BK=16, double-buffered ----
// MODE 0: coarse (A = 16x16 patches of f2, K=16384) -> out (no bias)
// MODE 1: detail (A =  8x8  patches of f2, K= 4096) -> g_dmap (no bias)
// MODE 2: merge  (A = gathered dmap rows,  K= 3072) -> out (no bias)
#define LDA 20   // padded smem leading dim (floats), multiple of 4

template<int MODE>
__global__ __launch_bounds__(256)
void wmma_gemm(const float* __restrict__ W, float* __restrict__ out)
{
    constexpr int K   = (MODE == 0) ? 16384 : ((MODE == 1) ? 4096 : 3072);
    constexpr int NCH = K / 16;

    __shared__ __align__(16) float As[2][128*LDA];
    __shared__ __align__(16) float Bs[2][128*LDA];

    const int tid = threadIdx.x;
    const int wid = tid >> 5;
    const int bm = blockIdx.y, bn = blockIdx.x;

    // ---- global load mapping: row lr (0..127), half selects k sub-8 ----
    const int lr = tid >> 1;
    const int half = tid & 1;
    const int arow = bm * 128 + lr;
    const int brow = bn * 128 + lr;

    int baseA = 0, baseY = 0, baseX = 0;
    if (MODE == 0) {
        int b = arow / 576; int cell = arow % 576;
        baseA = ((b*64)*HH + (cell/24)*16)*HH + (cell%24)*16;
    } else if (MODE == 1) {
        int b = arow / 2304; int r2 = arow % 2304;
        baseA = ((b*64)*HH + (r2/48)*8)*HH + (r2%48)*8;
    } else {
        int cell = g_topk[arow];
        int b = arow >> 6;
        baseY = b*48 + 2*(cell / 24);
        baseX = 2*(cell % 24);
    }
    const float* wp = W + (long)brow * K;

    // warp tile: 64(m) x 32(n)
    const int wm = (wid & 1) * 64;
    const int wn = (wid >> 1) * 32;

    wmma::fragment<wmma::accumulator, 16, 16, 8, float> acc[4][2];
#pragma unroll
    for (int i = 0; i < 4; i++)
#pragma unroll
        for (int j = 0; j < 2; j++) wmma::fill_fragment(acc[i][j], 0.f);

    const uint32_t soff = lr*LDA + half*8;

    float4 av[2], bv[2];
    // prefetch chunk 0
    {
        const int kc = 0;
#pragma unroll
        for (int j = 0; j < 2; j++) {
            const int k0 = kc + half*8 + j*4;
            const float* ap;
            if (MODE == 0) {
                int c = k0 >> 8; int rem = k0 & 255;
                ap = g_f2 + baseA + c*(HH*HH) + (rem >> 4)*HH + (rem & 15);
            } else if (MODE == 1) {
                int c = k0 >> 6; int rem = k0 & 63;
                ap = g_f2 + baseA + c*(HH*HH) + (rem >> 3)*HH + (rem & 7);
            } else {
                int dyx = k0 / 768; int e = k0 - dyx*768;
                ap = g_dmap + ((long)((baseY + (dyx >> 1))*48 + baseX + (dyx & 1)))*768 + e;
            }
            av[j] = *(const float4*)ap;
            bv[j] = *(const float4*)(wp + k0);
        }
    }

    for (int i = 0; i < NCH; i++) {
        const int buf = i & 1;
        // store current chunk (convert to tf32)
#pragma unroll
        for (int j = 0; j < 2; j++) {
            float4 a = av[j], b = bv[j];
            a.x = wmma::__float_to_tf32(a.x); a.y = wmma::__float_to_tf32(a.y);
            a.z = wmma::__float_to_tf32(a.z); a.w = wmma::__float_to_tf32(a.w);
            b.x = wmma::__float_to_tf32(b.x); b.y = wmma::__float_to_tf32(b.y);
            b.z = wmma::__float_to_tf32(b.z); b.w = wmma::__float_to_tf32(b.w);
            *(float4*)&As[buf][soff + j*4] = a;
            *(float4*)&Bs[buf][soff + j*4] = b;
        }
        __syncthreads();

        // prefetch next chunk
        if (i + 1 < NCH) {
            const int kc = (i + 1) * 16;
#pragma unroll
            for (int j = 0; j < 2; j++) {
                const int k0 = kc + half*8 + j*4;
                const float* ap;
                if (MODE == 0) {
                    int c = k0 >> 8; int rem = k0 & 255;
                    ap = g_f2 + baseA + c*(HH*HH) + (rem >> 4)*HH + (rem & 15);
                } else if (MODE == 1) {
                    int c = k0 >> 6; int rem = k0 & 63;
                    ap = g_f2 + baseA + c*(HH*HH) + (rem >> 3)*HH + (rem & 7);
                } else {
                    int dyx = k0 / 768; int e = k0 - dyx*768;
                    ap = g_dmap + ((long)((baseY + (dyx >> 1))*48 + baseX + (dyx & 1)))*768 + e;
                }
                av[j] = *(const float4*)ap;
                bv[j] = *(const float4*)(wp + k0);
            }
        }

        // compute 2 k-steps of 8
#pragma unroll
        for (int ks = 0; ks < 2; ks++) {
            wmma::fragment<wmma::matrix_a, 16, 16, 8, wmma::precision::tf32, wmma::row_major> af[4];
            wmma::fragment<wmma::matrix_b, 16, 16, 8, wmma::precision::tf32, wmma::col_major> bf[2];
#pragma unroll
            for (int mi = 0; mi < 4; mi++)
                wmma::load_matrix_sync(af[mi], &As[buf][(wm + 16*mi)*LDA + ks*8], LDA);
#pragma unroll
            for (int nj = 0; nj < 2; nj++)
                wmma::load_matrix_sync(bf[nj], &Bs[buf][(wn + 16*nj)*LDA + ks*8], LDA);
#pragma unroll
            for (int mi = 0; mi < 4; mi++)
#pragma unroll
                for (int nj = 0; nj < 2; nj++)
                    wmma::mma_sync(acc[mi][nj], af[mi], bf[nj], acc[mi][nj]);
        }
    }

    float* op = (MODE == 1) ? g_dmap : out;
#pragma unroll
    for (int mi = 0; mi < 4; mi++)
#pragma unroll
        for (int nj = 0; nj < 2; nj++) {
            long mrow = (long)bm*128 + wm + 16*mi;
            int ncol = bn*128 + wn + 16*nj;
            wmma::store_matrix_sync(&op[mrow*768 + ncol], acc[mi][nj], 768, wmma::mem_row_major);
        }
}

// ---------------- bias helpers ----------------
__global__ void add_bias_kernel(float* __restrict__ out, const float* __restrict__ bias, int n4)
{
    int i = blockIdx.x * blockDim.x + threadIdx.x;
    if (i >= n4) return;
    float4 v = ((float4*)out)[i];
    int nb = (i * 4) % 768;
    float4 b = *(const float4*)&bias[nb];
    v.x += b.x; v.y += b.y; v.z += b.z; v.w += b.w;
    ((float4*)out)[i] = v;
}

__global__ void add_mbias_kernel(float* __restrict__ out, int n4)
{
    int i = blockIdx.x * blockDim.x + threadIdx.x;
    if (i >= n4) return;
    float4 v = ((float4*)out)[i];
    int nb = (i * 4) % 768;
    float4 b = *(const float4*)&g_mbias[nb];
    v.x += b.x; v.y += b.y; v.z += b.z; v.w += b.w;
    ((float4*)out)[i] = v;
}

// g_mbias[n] = merge_b[n] + sum_k detail_b[k % 768] * merge_w[n][k]
__global__ void mbias_kernel(const float* __restrict__ merge_w, const float* __restrict__ merge_b,
                             const float* __restrict__ detail_b)
{
    const int n = blockIdx.x;
    const int tid = threadIdx.x;
    const float* wr = merge_w + (long)n * 3072;
    float s = 0.f;
    for (int k = tid; k < 3072; k += 256)
        s = fmaf(detail_b[k % 768], wr[k], s);
    __shared__ float red[256];
    red[tid] = s;
    __syncthreads();
    for (int off = 128; off > 0; off >>= 1) {
        if (tid < off) red[tid] += red[tid + off];
        __syncthreads();
    }
    if (tid == 0) g_mbias[n] = merge_b[n] + red[0];
}

// ---------------- per-patch variance score (coalesced float4) ----------------
__global__ void score_kernel()
{
    const int bi = blockIdx.x;           // b*576 + cell
    const int b = bi / 576, cell = bi % 576;
    const int gy = cell / 24, gx = cell % 24;
    const int tid = threadIdx.x;
    const int c = tid >> 2, q = tid & 3;  // q = column quarter
    const float* base = g_f2 + ((b*64 + c)*HH + gy*16)*HH + gx*16 + q*4;
    float s = 0.f, ss = 0.f;
#pragma unroll
    for (int i = 0; i < 16; i++) {
        float4 v = *(const float4*)(base + i*HH);
        s += v.x + v.y + v.z + v.w;
        ss = fmaf(v.x, v.x, ss); ss = fmaf(v.y, v.y, ss);
        ss = fmaf(v.z, v.z, ss); ss = fmaf(v.w, v.w, ss);
    }
    s  += __shfl_down_sync(0xffffffffu, s, 2);
    s  += __shfl_down_sync(0xffffffffu, s, 1);
    ss += __shfl_down_sync(0xffffffffu, ss, 2);
    ss += __shfl_down_sync(0xffffffffu, ss, 1);
    __shared__ float cv[64];
    if ((tid & 3) == 0) {
        float mean = s * (1.f/256.f);
        cv[c] = ss * (1.f/256.f) - mean*mean;
    }
    __syncthreads();
    if (tid < 32) {
        float v = cv[tid] + cv[tid + 32];
        for (int off = 16; off > 0; off >>= 1)
            v += __shfl_down_sync(0xffffffffu, v, off);
        if (tid == 0) g_scores[bi] = v * (1.f/64.f);
    }
}

// ---------------- top-64 of 576, descending, ties -> lowest index ----------------
__global__ void topk_kernel(float* __restrict__ out_idx)
{
    const int b = blockIdx.x, tid = threadIdx.x;
    __shared__ float s[576];
    __shared__ float rv[256];
    __shared__ int   ri[256];
    for (int i = tid; i < 576; i += 256) s[i] = g_scores[b*576 + i];
    __syncthreads();
    for (int k = 0; k < 64; k++) {
        float bv = s[tid]; int bidx = tid;
        if (tid + 256 < 576) { float v = s[tid + 256]; if (v > bv) { bv = v; bidx = tid + 256; } }
        if (tid + 512 < 576) { float v = s[tid + 512]; if (v > bv) { bv = v; bidx = tid + 512; } }
        rv[tid] = bv; ri[tid] = bidx;
        __syncthreads();
        for (int off = 128; off > 0; off >>= 1) {
            if (tid < off) {
                float v2 = rv[tid + off]; int i2 = ri[tid + off];
                if (v2 > rv[tid] || (v2 == rv[tid] && i2 < ri[tid])) { rv[tid] = v2; ri[tid] = i2; }
            }
            __syncthreads();
        }
        if (tid == 0) {
            int best = ri[0];
            g_topk[b*64 + k] = best;
            out_idx[b*64 + k] = (float)best;
            s[best] = -3.0e38f;
        }
        __syncthreads();
    }
}

// ---------------- launch ----------------
extern "C" void kernel_launch(void* const* d_in, const int* in_sizes, int n_in,
                              void* d_out, int out_size)
{
    (void)in_sizes; (void)n_in; (void)out_size;
    const float* x        = (const float*)d_in[0];
    const float* conv1_w  = (const float*)d_in[1];
    const float* bn1_g    = (const float*)d_in[2];
    const float* bn1_b    = (const float*)d_in[3];
    const float* bn1_m    = (const float*)d_in[4];
    const float* bn1_v    = (const float*)d_in[5];
    const float* conv2_w  = (const float*)d_in[6];
    const float* bn2_g    = (const float*)d_in[7];
    const float* bn2_b    = (const float*)d_in[8];
    const float* bn2_m    = (const float*)d_in[9];
    const float* bn2_v    = (const float*)d_in[10];
    const float* coarse_w = (const float*)d_in[11];
    const float* coarse_b = (const float*)d_in[12];
    const float* detail_w = (const float*)d_in[13];
    const float* detail_b = (const float*)d_in[14];
    const float* merge_w  = (const float*)d_in[15];
    const float* merge_b  = (const float*)d_in[16];
    float* out = (float*)d_out;

    const long OFF1 = 16L*576*768;            // coarse tokens
    const long OFF2 = OFF1 + 16L*64*768;      // detail tokens

    conv1_kernel<<<dim3(24,24,16), dim3(16,16)>>>(x, conv1_w, bn1_g, bn1_b, bn1_m, bn1_v);
    conv2_kernel<<<dim3(24,6,64),  dim3(16,16)>>>(conv2_w, bn2_g, bn2_b, bn2_m, bn2_v);

    // effective merge bias (independent of stem; run early)
    mbias_kernel<<<768, 256>>>(merge_w, merge_b, detail_b);

    // coarse tokens -> out[0 .. OFF1), then += coarse_b
    wmma_gemm<0><<<dim3(6,72), 256>>>(coarse_w, out);
    add_bias_kernel<<<(9216*768/4 + 255)/256, 256>>>(out, coarse_b, 9216*768/4);

    // variance scores + top-k (writes float idx to out[OFF2..])
    score_kernel<<<9216, 256>>>();
    topk_kernel<<<16, 256>>>(out + OFF2);

    // detail map (no bias) -> g_dmap
    wmma_gemm<1><<<dim3(6,288), 256>>>(detail_w, nullptr);

    // merge only the selected K=64 cells -> out[OFF1 .. OFF2), then += g_mbias
    wmma_gemm<2><<<dim3(6,8), 256>>>(merge_w, out + OFF1);
    add_mbias_kernel<<<(1024*768/4 + 255)/256, 256>>>(out + OFF1, 1024*768/4);
}

// round 4
// speedup vs baseline: 1.5637x; 1.3332x over previous
#include <cuda_runtime.h>
#include <math.h>
#include <stdint.h>
#include <mma.h>

using namespace nvcuda;

// ---------------- problem constants ----------------
#define HH 384
#define BB 16
#define CI 64
#define EE 768

// ---------------- scratch (device globals, no allocation) ----------------
__device__ float g_f1[(size_t)BB*CI*HH*HH];          // after conv1+bn+gelu
__device__ float g_f2[(size_t)BB*CI*HH*HH];          // after conv2+bn+gelu
__device__ float g_dgath[(size_t)4096*EE];           // gathered detail conv outputs (no bias)
__device__ float g_scores[BB*576];
__device__ int   g_topk[BB*64];
__device__ float g_mbias[EE];                        // effective merge bias

__device__ __forceinline__ float gelu_f(float v) { return v * normcdff(v); }

// ---------------- conv1: 3->64, 3x3, pad1, + BN + GELU ----------------
__global__ void conv1_kernel(const float* __restrict__ x, const float* __restrict__ w,
                             const float* __restrict__ gma, const float* __restrict__ bta,
                             const float* __restrict__ mu,  const float* __restrict__ var)
{
    __shared__ float xs[3][18][18];
    __shared__ float ws[64*27];
    __shared__ float sc[64], sh[64];
    const int tid = threadIdx.y * 16 + threadIdx.x;
    const int b  = blockIdx.z;
    const int y0 = blockIdx.y * 16, x0 = blockIdx.x * 16;

    for (int i = tid; i < 3*18*18; i += 256) {
        int ci = i / 324, r = (i % 324) / 18, cc = i % 18;
        int yy = y0 - 1 + r, xx = x0 - 1 + cc;
        float v = 0.f;
        if (yy >= 0 && yy < HH && xx >= 0 && xx < HH)
            v = x[((b*3 + ci)*HH + yy)*HH + xx];
        xs[ci][r][cc] = v;
    }
    for (int i = tid; i < 64*27; i += 256) ws[i] = w[i];
    if (tid < 64) {
        float s = gma[tid] * rsqrtf(var[tid] + 1e-5f);
        sc[tid] = s; sh[tid] = bta[tid] - mu[tid] * s;
    }
    __syncthreads();

    float win[27];
#pragma unroll
    for (int ci = 0; ci < 3; ci++)
#pragma unroll
        for (int ky = 0; ky < 3; ky++)
#pragma unroll
            for (int kx = 0; kx < 3; kx++)
                win[(ci*3 + ky)*3 + kx] = xs[ci][threadIdx.y + ky][threadIdx.x + kx];

    const int y = y0 + threadIdx.y, xg = x0 + threadIdx.x;
    for (int oc = 0; oc < 64; oc++) {
        float acc = 0.f;
#pragma unroll
        for (int i = 0; i < 27; i++) acc = fmaf(ws[oc*27 + i], win[i], acc);
        float t = acc * sc[oc] + sh[oc];
        g_f1[((b*64 + oc)*HH + y)*HH + xg] = gelu_f(t);
    }
}

// ---------------- conv2: 64->64, 3x3, pad1, + BN + GELU ----------------
__global__ __launch_bounds__(256, 2)
void conv2_kernel(const float* __restrict__ w,
                  const float* __restrict__ gma, const float* __restrict__ bta,
                  const float* __restrict__ mu,  const float* __restrict__ var)
{
    __shared__ float ti[66][18];
    __shared__ float wsm[144];
    __shared__ float sc[16], sh[16];
    const int tx = threadIdx.x, ty = threadIdx.y;
    const int tid = ty * 16 + tx;
    const int bz = blockIdx.z;
    const int b = bz >> 2, ocb = (bz & 3) * 16;
    const int y0 = blockIdx.y * 64, x0 = blockIdx.x * 16;

    if (tid < 16) {
        int oc = ocb + tid;
        float s = gma[oc] * rsqrtf(var[oc] + 1e-5f);
        sc[tid] = s; sh[tid] = bta[oc] - mu[oc] * s;
    }

    float acc[4][16];
#pragma unroll
    for (int r = 0; r < 4; r++)
#pragma unroll
        for (int o = 0; o < 16; o++) acc[r][o] = 0.f;

    for (int ci = 0; ci < 64; ci++) {
        __syncthreads();
        for (int i = tid; i < 66*18; i += 256) {
            int r = i / 18, cc = i % 18;
            int yy = y0 - 1 + r, xx = x0 - 1 + cc;
            float v = 0.f;
            if (yy >= 0 && yy < HH && xx >= 0 && xx < HH)
                v = g_f1[((b*64 + ci)*HH + yy)*HH + xx];
            ti[r][cc] = v;
        }
        if (tid < 144) {
            int o = tid / 9, j = tid % 9;
            wsm[tid] = w[(ocb + o)*576 + ci*9 + j];
        }
        __syncthreads();

        float win[4][9];
#pragma unroll
        for (int r = 0; r < 4; r++)
#pragma unroll
            for (int ky = 0; ky < 3; ky++)
#pragma unroll
                for (int kx = 0; kx < 3; kx++)
                    win[r][ky*3 + kx] = ti[ty + 16*r + ky][tx + kx];

#pragma unroll
        for (int o = 0; o < 16; o++) {
#pragma unroll
            for (int j = 0; j < 9; j++) {
                float wv = wsm[o*9 + j];
#pragma unroll
                for (int r = 0; r < 4; r++)
                    acc[r][o] = fmaf(wv, win[r][j], acc[r][o]);
            }
        }
    }

#pragma unroll
    for (int r = 0; r < 4; r++) {
        int y = y0 + ty + 16*r;
#pragma unroll
        for (int o = 0; o < 16; o++) {
            float t = acc[r][o] * sc[o] + sh[o];
            g_f2[((b*64 + ocb + o)*HH + y)*HH + x0 + tx] = gelu_f(t);
        }
    }
}

// ---------------- WMMA tf32 implicit GEMM: 128x128 tile, BK=32, double-buffered ----
// MODE 0: coarse  (A = 16x16 patches of f2, K=16384, M=9216) -> out
// MODE 1: detail@topk (A = 8x8 patches at gathered positions, K=4096, M=4096) -> g_dgath
// MODE 2: merge   (A = g_dgath rows, K=3072, M=1024) -> out
#define LDA 36   // padded smem leading dim (floats); 36*4=144B keeps rows 16B-aligned

template<int MODE>
__global__ __launch_bounds__(256, 2)
void wmma_gemm(const float* __restrict__ W, float* __restrict__ out)
{
    constexpr int K   = (MODE == 0) ? 16384 : ((MODE == 1) ? 4096 : 3072);
    constexpr int NCH = K / 32;

    __shared__ __align__(16) float As[2][128*LDA];
    __shared__ __align__(16) float Bs[2][128*LDA];

    const int tid = threadIdx.x;
    const int wid = tid >> 5;
    const int bm = blockIdx.y, bn = blockIdx.x;

    // ---- global load mapping: row lr (0..127), half selects k sub-16 ----
    const int lr = tid >> 1;
    const int half = tid & 1;
    const int arow = bm * 128 + lr;
    const int brow = bn * 128 + lr;

    long baseA = 0;
    if (MODE == 0) {
        int b = arow / 576; int cell = arow % 576;
        baseA = ((long)(b*64)*HH + (cell/24)*16)*HH + (cell%24)*16;
    } else if (MODE == 1) {
        int b = arow >> 8, kk = (arow >> 2) & 63, dyx = arow & 3;
        int cell = g_topk[b*64 + kk];
        int y48 = 2*(cell/24) + (dyx >> 1);
        int x48 = 2*(cell%24) + (dyx & 1);
        baseA = ((long)(b*64)*HH + y48*8)*HH + x48*8;
    } else {
        baseA = (long)arow * 3072;
    }
    const float* wp = W + (long)brow * K;

    // warp tile: 64(m) x 32(n)
    const int wm = (wid & 1) * 64;
    const int wn = (wid >> 1) * 32;

    wmma::fragment<wmma::accumulator, 16, 16, 8, float> acc[4][2];
#pragma unroll
    for (int i = 0; i < 4; i++)
#pragma unroll
        for (int j = 0; j < 2; j++) wmma::fill_fragment(acc[i][j], 0.f);

    const uint32_t soff = lr*LDA + half*16;

    // helper to load + convert + store one chunk into buffer `buf`
    auto load_chunk = [&](int kc, int buf) {
#pragma unroll
        for (int j = 0; j < 4; j++) {
            const int k0 = kc + half*16 + j*4;
            const float* ap;
            if (MODE == 0) {
                int c = k0 >> 8; int rem = k0 & 255;
                ap = g_f2 + baseA + (long)c*(HH*HH) + (rem >> 4)*HH + (rem & 15);
            } else if (MODE == 1) {
                int c = k0 >> 6; int rem = k0 & 63;
                ap = g_f2 + baseA + (long)c*(HH*HH) + (rem >> 3)*HH + (rem & 7);
            } else {
                ap = g_dgath + baseA + k0;
            }
            float4 a = *(const float4*)ap;
            float4 b = *(const float4*)(wp + k0);
            a.x = wmma::__float_to_tf32(a.x); a.y = wmma::__float_to_tf32(a.y);
            a.z = wmma::__float_to_tf32(a.z); a.w = wmma::__float_to_tf32(a.w);
            b.x = wmma::__float_to_tf32(b.x); b.y = wmma::__float_to_tf32(b.y);
            b.z = wmma::__float_to_tf32(b.z); b.w = wmma::__float_to_tf32(b.w);
            *(float4*)&As[buf][soff + j*4] = a;
            *(float4*)&Bs[buf][soff + j*4] = b;
        }
    };

    load_chunk(0, 0);
    __syncthreads();

    for (int i = 0; i < NCH; i++) {
        const int buf = i & 1;
        // write next chunk into the other buffer while computing this one
        if (i + 1 < NCH) load_chunk((i + 1) * 32, buf ^ 1);

#pragma unroll
        for (int ks = 0; ks < 4; ks++) {
            wmma::fragment<wmma::matrix_a, 16, 16, 8, wmma::precision::tf32, wmma::row_major> af[4];
            wmma::fragment<wmma::matrix_b, 16, 16, 8, wmma::precision::tf32, wmma::col_major> bf[2];
#pragma unroll
            for (int mi = 0; mi < 4; mi++)
                wmma::load_matrix_sync(af[mi], &As[buf][(wm + 16*mi)*LDA + ks*8], LDA);
#pragma unroll
            for (int nj = 0; nj < 2; nj++)
                wmma::load_matrix_sync(bf[nj], &Bs[buf][(wn + 16*nj)*LDA + ks*8], LDA);
#pragma unroll
            for (int mi = 0; mi < 4; mi++)
#pragma unroll
                for (int nj = 0; nj < 2; nj++)
                    wmma::mma_sync(acc[mi][nj], af[mi], bf[nj], acc[mi][nj]);
        }
        __syncthreads();
    }

    float* op = (MODE == 1) ? g_dgath : out;
#pragma unroll
    for (int mi = 0; mi < 4; mi++)
#pragma unroll
        for (int nj = 0; nj < 2; nj++) {
            long mrow = (long)bm*128 + wm + 16*mi;
            int ncol = bn*128 + wn + 16*nj;
            wmma::store_matrix_sync(&op[mrow*768 + ncol], acc[mi][nj], 768, wmma::mem_row_major);
        }
}

// ---------------- bias helpers ----------------
__global__ void add_bias_kernel(float* __restrict__ out, const float* __restrict__ bias, int n4)
{
    int i = blockIdx.x * blockDim.x + threadIdx.x;
    if (i >= n4) return;
    float4 v = ((float4*)out)[i];
    int nb = (i * 4) % 768;
    float4 b = *(const float4*)&bias[nb];
    v.x += b.x; v.y += b.y; v.z += b.z; v.w += b.w;
    ((float4*)out)[i] = v;
}

__global__ void add_mbias_kernel(float* __restrict__ out, int n4)
{
    int i = blockIdx.x * blockDim.x + threadIdx.x;
    if (i >= n4) return;
    float4 v = ((float4*)out)[i];
    int nb = (i * 4) % 768;
    float4 b = *(const float4*)&g_mbias[nb];
    v.x += b.x; v.y += b.y; v.z += b.z; v.w += b.w;
    ((float4*)out)[i] = v;
}

// g_mbias[n] = merge_b[n] + sum_k detail_b[k % 768] * merge_w[n][k]
__global__ void mbias_kernel(const float* __restrict__ merge_w, const float* __restrict__ merge_b,
                             const float* __restrict__ detail_b)
{
    const int n = blockIdx.x;
    const int tid = threadIdx.x;
    const float* wr = merge_w + (long)n * 3072;
    float s = 0.f;
    for (int k = tid; k < 3072; k += 256)
        s = fmaf(detail_b[k % 768], wr[k], s);
    __shared__ float red[256];
    red[tid] = s;
    __syncthreads();
    for (int off = 128; off > 0; off >>= 1) {
        if (tid < off) red[tid] += red[tid + off];
        __syncthreads();
    }
    if (tid == 0) g_mbias[n] = merge_b[n] + red[0];
}

// ---------------- per-patch variance score (coalesced float4) ----------------
__global__ void score_kernel()
{
    const int bi = blockIdx.x;           // b*576 + cell
    const int b = bi / 576, cell = bi % 576;
    const int gy = cell / 24, gx = cell % 24;
    const int tid = threadIdx.x;
    const int c = tid >> 2, q = tid & 3;  // q = column quarter
    const float* base = g_f2 + ((b*64 + c)*HH + gy*16)*HH + gx*16 + q*4;
    float s = 0.f, ss = 0.f;
#pragma unroll
    for (int i = 0; i < 16; i++) {
        float4 v = *(const float4*)(base + i*HH);
        s += v.x + v.y + v.z + v.w;
        ss = fmaf(v.x, v.x, ss); ss = fmaf(v.y, v.y, ss);
        ss = fmaf(v.z, v.z, ss); ss = fmaf(v.w, v.w, ss);
    }
    s  += __shfl_down_sync(0xffffffffu, s, 2);
    s  += __shfl_down_sync(0xffffffffu, s, 1);
    ss += __shfl_down_sync(0xffffffffu, ss, 2);
    ss += __shfl_down_sync(0xffffffffu, ss, 1);
    __shared__ float cv[64];
    if ((tid & 3) == 0) {
        float mean = s * (1.f/256.f);
        cv[c] = ss * (1.f/256.f) - mean*mean;
    }
    __syncthreads();
    if (tid < 32) {
        float v = cv[tid] + cv[tid + 32];
        for (int off = 16; off > 0; off >>= 1)
            v += __shfl_down_sync(0xffffffffu, v, off);
        if (tid == 0) g_scores[bi] = v * (1.f/64.f);
    }
}

// ---------------- top-64 of 576, descending, ties -> lowest index ----------------
__global__ void topk_kernel(float* __restrict__ out_idx)
{
    const int b = blockIdx.x, tid = threadIdx.x;
    __shared__ float s[576];
    __shared__ float rv[256];
    __shared__ int   ri[256];
    for (int i = tid; i < 576; i += 256) s[i] = g_scores[b*576 + i];
    __syncthreads();
    for (int k = 0; k < 64; k++) {
        float bv = s[tid]; int bidx = tid;
        if (tid + 256 < 576) { float v = s[tid + 256]; if (v > bv) { bv = v; bidx = tid + 256; } }
        if (tid + 512 < 576) { float v = s[tid + 512]; if (v > bv) { bv = v; bidx = tid + 512; } }
        rv[tid] = bv; ri[tid] = bidx;
        __syncthreads();
        for (int off = 128; off > 0; off >>= 1) {
            if (tid < off) {
                float v2 = rv[tid + off]; int i2 = ri[tid + off];
                if (v2 > rv[tid] || (v2 == rv[tid] && i2 < ri[tid])) { rv[tid] = v2; ri[tid] = i2; }
            }
            __syncthreads();
        }
        if (tid == 0) {
            int best = ri[0];
            g_topk[b*64 + k] = best;
            out_idx[b*64 + k] = (float)best;
            s[best] = -3.0e38f;
        }
        __syncthreads();
    }
}

// ---------------- launch ----------------
extern "C" void kernel_launch(void* const* d_in, const int* in_sizes, int n_in,
                              void* d_out, int out_size)
{
    (void)in_sizes; (void)n_in; (void)out_size;
    const float* x        = (const float*)d_in[0];
    const float* conv1_w  = (const float*)d_in[1];
    const float* bn1_g    = (const float*)d_in[2];
    const float* bn1_b    = (const float*)d_in[3];
    const float* bn1_m    = (const float*)d_in[4];
    const float* bn1_v    = (const float*)d_in[5];
    const float* conv2_w  = (const float*)d_in[6];
    const float* bn2_g    = (const float*)d_in[7];
    const float* bn2_b    = (const float*)d_in[8];
    const float* bn2_m    = (const float*)d_in[9];
    const float* bn2_v    = (const float*)d_in[10];
    const float* coarse_w = (const float*)d_in[11];
    const float* coarse_b = (const float*)d_in[12];
    const float* detail_w = (const float*)d_in[13];
    const float* detail_b = (const float*)d_in[14];
    const float* merge_w  = (const float*)d_in[15];
    const float* merge_b  = (const float*)d_in[16];
    float* out = (float*)d_out;

    const long OFF1 = 16L*576*768;            // coarse tokens
    const long OFF2 = OFF1 + 16L*64*768;      // detail tokens

    conv1_kernel<<<dim3(24,24,16), dim3(16,16)>>>(x, conv1_w, bn1_g, bn1_b, bn1_m, bn1_v);
    conv2_kernel<<<dim3(24,6,64),  dim3(16,16)>>>(conv2_w, bn2_g, bn2_b, bn2_m, bn2_v);

    // effective merge bias (independent of stem; run early)
    mbias_kernel<<<768, 256>>>(merge_w, merge_b, detail_b);

    // variance scores + top-k FIRST (they only need f2); writes float idx to out[OFF2..]
    score_kernel<<<9216, 256>>>();
    topk_kernel<<<16, 256>>>(out + OFF2);

    // coarse tokens -> out[0 .. OFF1), then += coarse_b
    wmma_gemm<0><<<dim3(6,72), 256>>>(coarse_w, out);
    add_bias_kernel<<<(9216*768/4 + 255)/256, 256>>>(out, coarse_b, 9216*768/4);

    // detail conv ONLY at gathered top-k positions -> g_dgath [4096 x 768]
    wmma_gemm<1><<<dim3(6,32), 256>>>(detail_w, nullptr);

    // merge the gathered rows -> out[OFF1 .. OFF2), then += g_mbias
    wmma_gemm<2><<<dim3(6,8), 256>>>(merge_w, out + OFF1);
    add_mbias_kernel<<<(1024*768/4 + 255)/256, 256>>>(out + OFF1, 1024*768/4);
}